// round 5
// baseline (speedup 1.0000x reference)
#include <cuda_runtime.h>
#include <math.h>

// MVKE collapsed-algebra implementation.
// B=8192, S=100, T=10, E=100, V=3, all fp32.
#define SCALE 0.1f
#define PADV  (-4294967295.0f)
#define NEGBIG (-3.402823466e38f)
#define GB 8                      // batches per stage-2 block

// Precomputed small tensors + scratch
__device__ float4 g_w2vT[100];          // (w2v[0][j], w2v[1][j], w2v[2][j], 0)
__device__ float  g_c1[4];
__device__ float  g_w4v[3 * 100];       // [v][j]
__device__ float  g_c2[4];
__device__ float  g_Y[8192 * 300];      // Y[b][v][e]

// ---------------------------------------------------------------------------
// K1: tiny precompute (single block)
// ---------------------------------------------------------------------------
__global__ void k_pre(const float* __restrict__ vk,
                      const float* __restrict__ fc1_w, const float* __restrict__ fc1_b,
                      const float* __restrict__ fc2_w, const float* __restrict__ fc2_b,
                      const float* __restrict__ fc3_w, const float* __restrict__ fc3_b,
                      const float* __restrict__ fc4_w, const float* __restrict__ fc4_b) {
    __shared__ float of2[3][100];
    __shared__ float of3[3][100];
    int tid = threadIdx.x;
    for (int i = tid; i < 300; i += blockDim.x) {
        int v = i / 100, e = i % 100;
        float a2 = fc2_b[e], a3 = fc3_b[e];
        #pragma unroll 4
        for (int j = 0; j < 100; j++) {
            float vv = vk[v * 100 + j];
            a2 = fmaf(vv, fc2_w[e * 100 + j], a2);
            a3 = fmaf(vv, fc3_w[e * 100 + j], a3);
        }
        of2[v][e] = a2;
        of3[v][e] = a3;
    }
    __syncthreads();
    for (int j = tid; j < 100; j += blockDim.x) {
        float a0 = 0.f, a1 = 0.f, a2 = 0.f;
        #pragma unroll 4
        for (int e = 0; e < 100; e++) {
            float w = fc1_w[e * 100 + j];
            a0 = fmaf(of2[0][e], w, a0);
            a1 = fmaf(of2[1][e], w, a1);
            a2 = fmaf(of2[2][e], w, a2);
        }
        g_w2vT[j] = make_float4(a0, a1, a2, 0.f);
    }
    for (int i = tid; i < 300; i += blockDim.x) {
        int v = i / 100, j = i % 100;
        float a = 0.f;
        #pragma unroll 4
        for (int e = 0; e < 100; e++) a = fmaf(of3[v][e], fc4_w[e * 100 + j], a);
        g_w4v[i] = a;
    }
    if (tid < 3) {
        float a = 0.f, b = 0.f;
        for (int e = 0; e < 100; e++) {
            a = fmaf(of2[tid][e], fc1_b[e], a);
            b = fmaf(of3[tid][e], fc4_b[e], b);
        }
        g_c1[tid] = a;
        g_c2[tid] = b;
    }
}

// ---------------------------------------------------------------------------
// K2: stage 1 — per-batch logits + softmax over S + weighted sum -> g_Y
// ---------------------------------------------------------------------------
__global__ __launch_bounds__(128) void k_stage1(const float* __restrict__ x) {
    __shared__ __align__(16) float xs[100 * 101];  // x[b], stride 101 (bank-safe both ways)
    __shared__ __align__(16) float pm[100 * 4];    // m1 -> sm1, [s][v] padded to 4
    __shared__ __align__(16) float4 w2s[100];
    __shared__ float red[8];                       // max[0..2], invsum[4..6]
    int tid = threadIdx.x;
    int b = blockIdx.x;

    // Load x[b] (40 KB) coalesced float4 -> padded smem
    const float4* xp = (const float4*)(x + (size_t)b * 10000);
    #pragma unroll 5
    for (int i = tid; i < 2500; i += 128) {
        float4 v = xp[i];
        int s = i / 25;
        int c = (i % 25) * 4;
        float* r = &xs[s * 101 + c];
        r[0] = v.x; r[1] = v.y; r[2] = v.z; r[3] = v.w;
    }
    if (tid < 100) w2s[tid] = g_w2vT[tid];
    __syncthreads();

    // m1[s][v] = (x[s]·w2v[v] + c1[v]) * scale, zero-row mask
    if (tid < 100) {
        const float* row = &xs[tid * 101];
        float a0 = 0.f, a1 = 0.f, a2 = 0.f, sa = 0.f;
        #pragma unroll 4
        for (int j = 0; j < 100; j++) {
            float xv = row[j];
            float4 w = w2s[j];
            sa += fabsf(xv);
            a0 = fmaf(xv, w.x, a0);
            a1 = fmaf(xv, w.y, a1);
            a2 = fmaf(xv, w.z, a2);
        }
        float m0 = (a0 + g_c1[0]) * SCALE;
        float m1 = (a1 + g_c1[1]) * SCALE;
        float m2 = (a2 + g_c1[2]) * SCALE;
        if (sa == 0.0f) { m0 = PADV; m1 = PADV; m2 = PADV; }
        float* o = &pm[tid * 4];
        o[0] = m0; o[1] = m1; o[2] = m2; o[3] = 0.f;
    }
    __syncthreads();

    // Per-v softmax stats over S=100 (warp v reduces virtual kernel v)
    if (tid < 96) {
        int v = tid >> 5;
        int lane = tid & 31;
        float vals[4];
        float mx = NEGBIG;
        #pragma unroll
        for (int i = 0; i < 4; i++) {
            int s = lane + i * 32;
            vals[i] = (s < 100) ? pm[s * 4 + v] : NEGBIG;
            mx = fmaxf(mx, vals[i]);
        }
        #pragma unroll
        for (int o = 16; o; o >>= 1) mx = fmaxf(mx, __shfl_xor_sync(0xffffffffu, mx, o));
        float sum = 0.f;
        #pragma unroll
        for (int i = 0; i < 4; i++) {
            int s = lane + i * 32;
            if (s < 100) sum += __expf(vals[i] - mx);
        }
        #pragma unroll
        for (int o = 16; o; o >>= 1) sum += __shfl_xor_sync(0xffffffffu, sum, o);
        if (lane == 0) { red[v] = mx; red[4 + v] = 1.0f / sum; }
    }
    __syncthreads();

    // sm1[s][v] normalized in place
    if (tid < 100) {
        float* o = &pm[tid * 4];
        o[0] = __expf(o[0] - red[0]) * red[4];
        o[1] = __expf(o[1] - red[1]) * red[5];
        o[2] = __expf(o[2] - red[2]) * red[6];
    }
    __syncthreads();

    // Y[b][v][e] = sum_s sm1[s][v] * x[s][e]
    if (tid < 100) {
        float a0 = 0.f, a1 = 0.f, a2 = 0.f;
        #pragma unroll 4
        for (int s = 0; s < 100; s++) {
            float xv = xs[s * 101 + tid];
            float4 w = *(const float4*)&pm[s * 4];
            a0 = fmaf(xv, w.x, a0);
            a1 = fmaf(xv, w.y, a1);
            a2 = fmaf(xv, w.z, a2);
        }
        float* yb = g_Y + (size_t)b * 300;
        yb[tid] = a0;
        yb[100 + tid] = a1;
        yb[200 + tid] = a2;
    }
}

// ---------------------------------------------------------------------------
// K3: stage 2 — ws1 mini-GEMM (f32x2 packed) + m2 softmax + output dot
// smem carve (floats):
//  fws   [100*102] fc1_w padded rows (8B-aligned pairs)
//  ysT2  [50*48]   Y pairs transposed: [jp][(g*3+v)*2 + {0,1}]
//  ws1s  [24*100]  ws1[g*3+v][e]
//  tgA   [8*1000]  tags
//  w4vs  [300], fb [100], c2s [4], m2s [240], dss [240], red2 [48]
// ---------------------------------------------------------------------------
__global__ __launch_bounds__(128) void k_stage2(const float* __restrict__ tag,
                                                const float* __restrict__ fc1_w,
                                                const float* __restrict__ fc1_b,
                                                float* __restrict__ out) {
    extern __shared__ __align__(16) float smem[];
    float* fws  = smem;              // 10200
    float* ysT2 = fws + 10200;       // 2400
    float* ws1s = ysT2 + 2400;       // 2400
    float* tgA  = ws1s + 2400;       // 8000
    float* w4vs = tgA + 8000;        // 300
    float* fb   = w4vs + 300;        // 100
    float* c2s  = fb + 100;          // 4
    float* m2s  = c2s + 4;           // 240
    float* dss  = m2s + 240;         // 240
    float* red2 = dss + 240;         // 48

    int tid = threadIdx.x;
    int b0 = blockIdx.x * GB;

    // fc1_w -> padded smem rows (stride 102 keeps float2 loads 8B aligned)
    const float4* fw4 = (const float4*)fc1_w;
    #pragma unroll 5
    for (int i = tid; i < 2500; i += 128) {
        float4 w = fw4[i];
        int e = i / 25, c = (i % 25) * 4;
        float* r = &fws[e * 102 + c];
        r[0] = w.x; r[1] = w.y; r[2] = w.z; r[3] = w.w;
    }
    // tags (contiguous copy)
    const float4* tp = (const float4*)(tag + (size_t)b0 * 1000);
    #pragma unroll 4
    for (int i = tid; i < GB * 250; i += 128) ((float4*)tgA)[i] = tp[i];
    // Y -> pair-transposed layout
    for (int i = tid; i < 1200; i += 128) {
        int g = i / 150, r = i % 150, v = r / 50, jp = r % 50;
        float2 val = *(const float2*)(g_Y + (size_t)(b0 + g) * 300 + v * 100 + jp * 2);
        float* dst = &ysT2[jp * 48 + (g * 3 + v) * 2];
        dst[0] = val.x; dst[1] = val.y;
    }
    for (int i = tid; i < 300; i += 128) w4vs[i] = g_w4v[i];
    if (tid < 100) fb[tid] = fc1_b[tid];
    if (tid < 3)   c2s[tid] = g_c2[tid];
    __syncthreads();

    // ws1[g][v][e] = sum_j Y[g][v][j] * fc1_w[e][j] + fc1_b[e]
    // thread e owns 24 packed accumulators; fma.rn.f32x2 over j pairs
    if (tid < 100) {
        unsigned long long acc[24];
        #pragma unroll
        for (int k = 0; k < 24; k++) acc[k] = 0ull;
        const float* fr = &fws[tid * 102];
        #pragma unroll 2
        for (int jp = 0; jp < 50; jp++) {
            unsigned long long w2 = *(const unsigned long long*)(fr + jp * 2);
            const ulonglong2* yr = (const ulonglong2*)&ysT2[jp * 48];
            #pragma unroll
            for (int p = 0; p < 12; p++) {
                ulonglong2 y = yr[p];
                asm("fma.rn.f32x2 %0, %1, %2, %0;" : "+l"(acc[2 * p])     : "l"(w2), "l"(y.x));
                asm("fma.rn.f32x2 %0, %1, %2, %0;" : "+l"(acc[2 * p + 1]) : "l"(w2), "l"(y.y));
            }
        }
        float bias = fb[tid];
        #pragma unroll
        for (int k = 0; k < 24; k++) {
            union { unsigned long long u; float2 f; } cv;
            cv.u = acc[k];
            ws1s[k * 100 + tid] = cv.f.x + cv.f.y + bias;
        }
    }
    __syncthreads();

    // m2[g][t][v] and d[g][t][v] dots — 240 triples across 128 threads
    for (int i = tid; i < 240; i += 128) {
        int g = i / 30, r = i % 30, t = r / 3, v = r % 3;
        const float* tr = &tgA[g * 1000 + t * 100];
        const float* wr = &w4vs[v * 100];
        const float* sr = &ws1s[(g * 3 + v) * 100];
        float am = 0.f, ad = 0.f;
        #pragma unroll 4
        for (int e = 0; e < 100; e++) {
            float te = tr[e];
            am = fmaf(te, wr[e], am);
            ad = fmaf(te, sr[e], ad);
        }
        m2s[i] = (am + c2s[v]) * SCALE;
        dss[i] = ad;
    }
    __syncthreads();

    // softmax over T per (g,v)
    if (tid < 24) {
        int g = tid / 3, v = tid % 3;
        float mx = NEGBIG;
        #pragma unroll
        for (int t = 0; t < 10; t++) mx = fmaxf(mx, m2s[g * 30 + t * 3 + v]);
        float s = 0.f;
        #pragma unroll
        for (int t = 0; t < 10; t++) s += __expf(m2s[g * 30 + t * 3 + v] - mx);
        red2[tid] = mx;
        red2[24 + tid] = 1.0f / s;
    }
    __syncthreads();

    // out[b][t] = sum_v sm2[t][v] * d[t][v]
    if (tid < 80) {
        int g = tid / 10, t = tid % 10;
        float o = 0.f;
        #pragma unroll
        for (int v = 0; v < 3; v++) {
            float w = __expf(m2s[g * 30 + t * 3 + v] - red2[g * 3 + v]) * red2[24 + g * 3 + v];
            o = fmaf(w, dss[g * 30 + t * 3 + v], o);
        }
        out[(size_t)(b0 + g) * 10 + t] = o;
    }
}

// ---------------------------------------------------------------------------
extern "C" void kernel_launch(void* const* d_in, const int* in_sizes, int n_in,
                              void* d_out, int out_size) {
    const float* x     = (const float*)d_in[0];
    const float* tag   = (const float*)d_in[1];
    const float* vk    = (const float*)d_in[2];
    const float* fc1_w = (const float*)d_in[3];
    const float* fc1_b = (const float*)d_in[4];
    const float* fc2_w = (const float*)d_in[5];
    const float* fc2_b = (const float*)d_in[6];
    const float* fc3_w = (const float*)d_in[7];
    const float* fc3_b = (const float*)d_in[8];
    const float* fc4_w = (const float*)d_in[9];
    const float* fc4_b = (const float*)d_in[10];
    float* out = (float*)d_out;

    const int SMEM2 = (10200 + 2400 + 2400 + 8000 + 300 + 100 + 4 + 240 + 240 + 48) * 4;
    cudaFuncSetAttribute(k_stage2, cudaFuncAttributeMaxDynamicSharedMemorySize, SMEM2);

    k_pre<<<1, 128>>>(vk, fc1_w, fc1_b, fc2_w, fc2_b, fc3_w, fc3_b, fc4_w, fc4_b);
    k_stage1<<<8192, 128>>>(x);
    k_stage2<<<8192 / GB, 128, SMEM2>>>(tag, fc1_w, fc1_b, out);
}

// round 11
// speedup vs baseline: 1.0916x; 1.0916x over previous
#include <cuda_runtime.h>
#include <math.h>

// MVKE collapsed-algebra implementation.
// B=8192, S=100, T=10, E=100, V=3, all fp32.
#define SCALE 0.1f
#define PADV  (-4294967295.0f)
#define NEGBIG (-3.402823466e38f)
#define GB 8                      // batches per stage-2 block

// Precomputed small tensors + scratch
__device__ float4 g_w2vT[100];          // (w2v[0][j], w2v[1][j], w2v[2][j], 0)
__device__ float  g_c1[4];
__device__ float  g_w4v[3 * 100];       // [v][j]
__device__ float  g_c2[4];
__device__ float  g_Y[8192 * 300];      // Y[b][v][e]

// ---------------------------------------------------------------------------
// K1: precompute (single block, 1024 threads, coalesced warp-dot pattern)
// ---------------------------------------------------------------------------
__global__ __launch_bounds__(1024) void k_pre(
        const float* __restrict__ vk,
        const float* __restrict__ fc1_w, const float* __restrict__ fc1_b,
        const float* __restrict__ fc2_w, const float* __restrict__ fc2_b,
        const float* __restrict__ fc3_w, const float* __restrict__ fc3_b,
        const float* __restrict__ fc4_w, const float* __restrict__ fc4_b) {
    __shared__ float of2s[300];     // [v][e]
    __shared__ float of3s[300];
    __shared__ float part1[1200];   // w2v partials [c][v][j], c=0..3
    __shared__ float fbs1[100];     // fc1_b
    int tid = threadIdx.x;
    int wid = tid >> 5;
    int lane = tid & 31;

    if (tid < 100) fbs1[tid] = fc1_b[tid];

    // Phase A: 600 dot products (of2, of3), one warp per dot, lanes over j.
    for (int d = wid; d < 600; d += 32) {
        int which = d / 300;            // 0 -> of2 (fc2), 1 -> of3 (fc3)
        int r = d % 300;
        int v = r / 100, e = r % 100;
        const float* W = which ? fc3_w : fc2_w;
        const float* vrow = vk + v * 100;
        const float* wrow = W + e * 100;
        float a = 0.f;
        #pragma unroll
        for (int k = 0; k < 4; k++) {
            int j = lane + k * 32;
            if (j < 100) a = fmaf(vrow[j], wrow[j], a);
        }
        #pragma unroll
        for (int o = 16; o; o >>= 1) a += __shfl_xor_sync(0xffffffffu, a, o);
        if (lane == 0) {
            float bias = which ? fc3_b[e] : fc2_b[e];
            (which ? of3s : of2s)[r] = a + bias;
        }
    }
    __syncthreads();

    // Phase B (concurrent thread groups):
    // [0,400): w2v partials — c = e-chunk of 25, j coalesced across threads.
    if (tid < 400) {
        int c = tid / 100, j = tid % 100;
        int e0 = c * 25;
        float p0 = 0.f, p1 = 0.f, p2 = 0.f;
        #pragma unroll 5
        for (int e = e0; e < e0 + 25; e++) {
            float w = fc1_w[e * 100 + j];       // coalesced across j
            p0 = fmaf(of2s[e], w, p0);
            p1 = fmaf(of2s[100 + e], w, p1);
            p2 = fmaf(of2s[200 + e], w, p2);
        }
        part1[(c * 3 + 0) * 100 + j] = p0;
        part1[(c * 3 + 1) * 100 + j] = p1;
        part1[(c * 3 + 2) * 100 + j] = p2;
    }
    // [512,812): w4v — full e loop, j coalesced across threads.
    else if (tid >= 512 && tid < 812) {
        int d = tid - 512;
        int v = d / 100, j = d % 100;
        float a = 0.f;
        #pragma unroll 5
        for (int e = 0; e < 100; e++)
            a = fmaf(of3s[v * 100 + e], fc4_w[e * 100 + j], a);
        g_w4v[d] = a;
    }
    // [896,899): c1;  [900,903): c2.
    else if (tid >= 896 && tid < 899) {
        int v = tid - 896;
        float a = 0.f;
        for (int e = 0; e < 100; e++) a = fmaf(of2s[v * 100 + e], fbs1[e], a);
        g_c1[v] = a;
    } else if (tid >= 900 && tid < 903) {
        int v = tid - 900;
        float a = 0.f;
        for (int e = 0; e < 100; e++) a = fmaf(of3s[v * 100 + e], fc4_b[e], a);
        g_c2[v] = a;
    }
    __syncthreads();

    // Phase C: reduce w2v partials -> g_w2vT
    if (tid < 100) {
        float a0 = 0.f, a1 = 0.f, a2 = 0.f;
        #pragma unroll
        for (int c = 0; c < 4; c++) {
            a0 += part1[(c * 3 + 0) * 100 + tid];
            a1 += part1[(c * 3 + 1) * 100 + tid];
            a2 += part1[(c * 3 + 2) * 100 + tid];
        }
        g_w2vT[tid] = make_float4(a0, a1, a2, 0.f);
    }
}

// ---------------------------------------------------------------------------
// K2: stage 1 — 256 threads, split-K half-dots, softmax-over-S fused, -> g_Y
// ---------------------------------------------------------------------------
__global__ __launch_bounds__(256) void k_stage1(const float* __restrict__ x) {
    __shared__ __align__(16) float xs[100 * 101];  // x[b], stride 101 (bank-safe both ways)
    __shared__ __align__(16) float pp[200 * 4];    // split-K partials [task][4]
    __shared__ __align__(16) float pm[100 * 4];    // m1 -> exp(m-mx), [s][v] padded to 4
    __shared__ __align__(16) float4 w2s[100];
    __shared__ float red[8];                       // max[0..2], invsum[4..6]
    int tid = threadIdx.x;
    int b = blockIdx.x;

    // Load x[b] (40 KB) coalesced float4 -> padded smem
    const float4* xp = (const float4*)(x + (size_t)b * 10000);
    #pragma unroll 3
    for (int i = tid; i < 2500; i += 256) {
        float4 v = xp[i];
        int s = i / 25;
        int c = (i % 25) * 4;
        float* r = &xs[s * 101 + c];
        r[0] = v.x; r[1] = v.y; r[2] = v.z; r[3] = v.w;
    }
    if (tid < 100) w2s[tid] = g_w2vT[tid];
    __syncthreads();

    // m1 half-dots: task = (half, s), 50-deep each.
    // Warp pattern: consecutive s, stride 101 -> banks s*5+j, gcd(5,32)=1 -> conflict-free.
    if (tid < 200) {
        int s = tid % 100;
        int h = tid / 100;
        const float* row = &xs[s * 101 + h * 50];
        const float4* wv = &w2s[h * 50];
        float a0 = 0.f, a1 = 0.f, a2 = 0.f, sa = 0.f;
        #pragma unroll 10
        for (int j = 0; j < 50; j++) {
            float xv = row[j];
            float4 w = wv[j];
            sa += fabsf(xv);
            a0 = fmaf(xv, w.x, a0);
            a1 = fmaf(xv, w.y, a1);
            a2 = fmaf(xv, w.z, a2);
        }
        float* o = &pp[tid * 4];
        o[0] = a0; o[1] = a1; o[2] = a2; o[3] = sa;
    }
    __syncthreads();

    // Combine halves -> m1[s][v] with zero-row mask
    if (tid < 100) {
        const float* p0 = &pp[tid * 4];
        const float* p1 = &pp[(tid + 100) * 4];
        float sa = p0[3] + p1[3];
        float m0 = (p0[0] + p1[0] + g_c1[0]) * SCALE;
        float m1 = (p0[1] + p1[1] + g_c1[1]) * SCALE;
        float m2 = (p0[2] + p1[2] + g_c1[2]) * SCALE;
        if (sa == 0.0f) { m0 = PADV; m1 = PADV; m2 = PADV; }
        float* o = &pm[tid * 4];
        o[0] = m0; o[1] = m1; o[2] = m2; o[3] = 0.f;
    }
    __syncthreads();

    // Per-v softmax stats over S=100 (warp v reduces virtual kernel v)
    if (tid < 96) {
        int v = tid >> 5;
        int lane = tid & 31;
        float vals[4];
        float mx = NEGBIG;
        #pragma unroll
        for (int i = 0; i < 4; i++) {
            int s = lane + i * 32;
            vals[i] = (s < 100) ? pm[s * 4 + v] : NEGBIG;
            mx = fmaxf(mx, vals[i]);
        }
        #pragma unroll
        for (int o = 16; o; o >>= 1) mx = fmaxf(mx, __shfl_xor_sync(0xffffffffu, mx, o));
        float sum = 0.f;
        #pragma unroll
        for (int i = 0; i < 4; i++) {
            int s = lane + i * 32;
            if (s < 100) sum += __expf(vals[i] - mx);
        }
        #pragma unroll
        for (int o = 16; o; o >>= 1) sum += __shfl_xor_sync(0xffffffffu, sum, o);
        if (lane == 0) { red[v] = mx; red[4 + v] = 1.0f / sum; }
    }
    __syncthreads();

    // pm := exp(m - mx) (unnormalized; invsum folded into final Y scaling)
    if (tid < 100) {
        float* o = &pm[tid * 4];
        o[0] = __expf(o[0] - red[0]);
        o[1] = __expf(o[1] - red[1]);
        o[2] = __expf(o[2] - red[2]);
    }
    __syncthreads();

    // Y half-sums: task = (half, e), 50 s each.
    // Column reads xs[s*101+e]: consecutive e, same s -> consecutive banks, conflict-free.
    if (tid < 200) {
        int e = tid % 100;
        int h = tid / 100;
        float a0 = 0.f, a1 = 0.f, a2 = 0.f;
        #pragma unroll 10
        for (int s = h * 50; s < h * 50 + 50; s++) {
            float xv = xs[s * 101 + e];
            float4 w = *(const float4*)&pm[s * 4];   // 16B broadcast
            a0 = fmaf(xv, w.x, a0);
            a1 = fmaf(xv, w.y, a1);
            a2 = fmaf(xv, w.z, a2);
        }
        float* o = &pp[tid * 4];
        o[0] = a0; o[1] = a1; o[2] = a2;
    }
    __syncthreads();

    // Combine + scale by invsum, store Y coalesced
    if (tid < 100) {
        const float* p0 = &pp[tid * 4];
        const float* p1 = &pp[(tid + 100) * 4];
        float* yb = g_Y + (size_t)b * 300;
        yb[tid]       = (p0[0] + p1[0]) * red[4];
        yb[100 + tid] = (p0[1] + p1[1]) * red[5];
        yb[200 + tid] = (p0[2] + p1[2]) * red[6];
    }
}

// ---------------------------------------------------------------------------
// K3: stage 2 — ws1 mini-GEMM (f32x2 packed) + m2 softmax + output dot
// ---------------------------------------------------------------------------
__global__ __launch_bounds__(128) void k_stage2(const float* __restrict__ tag,
                                                const float* __restrict__ fc1_w,
                                                const float* __restrict__ fc1_b,
                                                float* __restrict__ out) {
    extern __shared__ __align__(16) float smem[];
    float* fws  = smem;              // 10200
    float* ysT2 = fws + 10200;       // 2400
    float* ws1s = ysT2 + 2400;       // 2400
    float* tgA  = ws1s + 2400;       // 8000
    float* w4vs = tgA + 8000;        // 300
    float* fb   = w4vs + 300;        // 100
    float* c2s  = fb + 100;          // 4
    float* m2s  = c2s + 4;           // 240
    float* dss  = m2s + 240;         // 240
    float* red2 = dss + 240;         // 48

    int tid = threadIdx.x;
    int b0 = blockIdx.x * GB;

    // fc1_w -> padded smem rows (stride 102 keeps float2 loads 8B aligned)
    const float4* fw4 = (const float4*)fc1_w;
    #pragma unroll 5
    for (int i = tid; i < 2500; i += 128) {
        float4 w = fw4[i];
        int e = i / 25, c = (i % 25) * 4;
        float* r = &fws[e * 102 + c];
        r[0] = w.x; r[1] = w.y; r[2] = w.z; r[3] = w.w;
    }
    // tags (contiguous copy)
    const float4* tp = (const float4*)(tag + (size_t)b0 * 1000);
    #pragma unroll 4
    for (int i = tid; i < GB * 250; i += 128) ((float4*)tgA)[i] = tp[i];
    // Y -> pair-transposed layout
    for (int i = tid; i < 1200; i += 128) {
        int g = i / 150, r = i % 150, v = r / 50, jp = r % 50;
        float2 val = *(const float2*)(g_Y + (size_t)(b0 + g) * 300 + v * 100 + jp * 2);
        float* dst = &ysT2[jp * 48 + (g * 3 + v) * 2];
        dst[0] = val.x; dst[1] = val.y;
    }
    for (int i = tid; i < 300; i += 128) w4vs[i] = g_w4v[i];
    if (tid < 100) fb[tid] = fc1_b[tid];
    if (tid < 3)   c2s[tid] = g_c2[tid];
    __syncthreads();

    // ws1[g][v][e] = sum_j Y[g][v][j] * fc1_w[e][j] + fc1_b[e]
    if (tid < 100) {
        unsigned long long acc[24];
        #pragma unroll
        for (int k = 0; k < 24; k++) acc[k] = 0ull;
        const float* fr = &fws[tid * 102];
        #pragma unroll 2
        for (int jp = 0; jp < 50; jp++) {
            unsigned long long w2 = *(const unsigned long long*)(fr + jp * 2);
            const ulonglong2* yr = (const ulonglong2*)&ysT2[jp * 48];
            #pragma unroll
            for (int p = 0; p < 12; p++) {
                ulonglong2 y = yr[p];
                asm("fma.rn.f32x2 %0, %1, %2, %0;" : "+l"(acc[2 * p])     : "l"(w2), "l"(y.x));
                asm("fma.rn.f32x2 %0, %1, %2, %0;" : "+l"(acc[2 * p + 1]) : "l"(w2), "l"(y.y));
            }
        }
        float bias = fb[tid];
        #pragma unroll
        for (int k = 0; k < 24; k++) {
            union { unsigned long long u; float2 f; } cv;
            cv.u = acc[k];
            ws1s[k * 100 + tid] = cv.f.x + cv.f.y + bias;
        }
    }
    __syncthreads();

    // m2[g][t][v] and d[g][t][v] dots — 240 triples across 128 threads
    for (int i = tid; i < 240; i += 128) {
        int g = i / 30, r = i % 30, t = r / 3, v = r % 3;
        const float* tr = &tgA[g * 1000 + t * 100];
        const float* wr = &w4vs[v * 100];
        const float* sr = &ws1s[(g * 3 + v) * 100];
        float am = 0.f, ad = 0.f;
        #pragma unroll 4
        for (int e = 0; e < 100; e++) {
            float te = tr[e];
            am = fmaf(te, wr[e], am);
            ad = fmaf(te, sr[e], ad);
        }
        m2s[i] = (am + c2s[v]) * SCALE;
        dss[i] = ad;
    }
    __syncthreads();

    // softmax over T per (g,v)
    if (tid < 24) {
        int g = tid / 3, v = tid % 3;
        float mx = NEGBIG;
        #pragma unroll
        for (int t = 0; t < 10; t++) mx = fmaxf(mx, m2s[g * 30 + t * 3 + v]);
        float s = 0.f;
        #pragma unroll
        for (int t = 0; t < 10; t++) s += __expf(m2s[g * 30 + t * 3 + v] - mx);
        red2[tid] = mx;
        red2[24 + tid] = 1.0f / s;
    }
    __syncthreads();

    // out[b][t] = sum_v sm2[t][v] * d[t][v]
    if (tid < 80) {
        int g = tid / 10, t = tid % 10;
        float o = 0.f;
        #pragma unroll
        for (int v = 0; v < 3; v++) {
            float w = __expf(m2s[g * 30 + t * 3 + v] - red2[g * 3 + v]) * red2[24 + g * 3 + v];
            o = fmaf(w, dss[g * 30 + t * 3 + v], o);
        }
        out[(size_t)(b0 + g) * 10 + t] = o;
    }
}

// ---------------------------------------------------------------------------
extern "C" void kernel_launch(void* const* d_in, const int* in_sizes, int n_in,
                              void* d_out, int out_size) {
    const float* x     = (const float*)d_in[0];
    const float* tag   = (const float*)d_in[1];
    const float* vk    = (const float*)d_in[2];
    const float* fc1_w = (const float*)d_in[3];
    const float* fc1_b = (const float*)d_in[4];
    const float* fc2_w = (const float*)d_in[5];
    const float* fc2_b = (const float*)d_in[6];
    const float* fc3_w = (const float*)d_in[7];
    const float* fc3_b = (const float*)d_in[8];
    const float* fc4_w = (const float*)d_in[9];
    const float* fc4_b = (const float*)d_in[10];
    float* out = (float*)d_out;

    const int SMEM2 = (10200 + 2400 + 2400 + 8000 + 300 + 100 + 4 + 240 + 240 + 48) * 4;
    cudaFuncSetAttribute(k_stage2, cudaFuncAttributeMaxDynamicSharedMemorySize, SMEM2);

    k_pre<<<1, 1024>>>(vk, fc1_w, fc1_b, fc2_w, fc2_b, fc3_w, fc3_b, fc4_w, fc4_b);
    k_stage1<<<8192, 256>>>(x);
    k_stage2<<<8192 / GB, 128, SMEM2>>>(tag, fc1_w, fc1_b, out);
}

// round 15
// speedup vs baseline: 1.1328x; 1.0377x over previous
#include <cuda_runtime.h>
#include <math.h>

// MVKE collapsed-algebra implementation.
// B=8192, S=100, T=10, E=100, V=3, all fp32.
#define SCALE 0.1f
#define PADV  (-4294967295.0f)
#define NEGBIG (-3.402823466e38f)
#define GB 8                      // batches per stage-2 block

// Precomputed small tensors + scratch
__device__ float4 g_w2vT[100];          // (w2v[0][j], w2v[1][j], w2v[2][j], 0)
__device__ float  g_c1[4];
__device__ float  g_w4v[3 * 100];       // [v][j]
__device__ float  g_c2[4];
__device__ float  g_of2[300];           // of2[v][e]
__device__ float  g_of3[300];           // of3[v][e]
__device__ float  g_Y[8192 * 300];      // Y[b][v][e]

// ---------------------------------------------------------------------------
// K1a: of2/of3 — 600 length-100 dots, one warp each, 75 blocks (600 warps) exact
// ---------------------------------------------------------------------------
__global__ __launch_bounds__(256) void k_pre_a(
        const float* __restrict__ vk,
        const float* __restrict__ fc2_w, const float* __restrict__ fc2_b,
        const float* __restrict__ fc3_w, const float* __restrict__ fc3_b) {
    int gw = blockIdx.x * 8 + (threadIdx.x >> 5);   // 0..599, no partial warps
    int lane = threadIdx.x & 31;
    int which = gw / 300;
    int r = gw % 300;
    int v = r / 100, e = r % 100;
    const float* W = which ? fc3_w : fc2_w;
    const float* vrow = vk + v * 100;
    const float* wrow = W + e * 100;
    float a = 0.f;
    #pragma unroll
    for (int k = 0; k < 4; k++) {
        int j = lane + k * 32;
        if (j < 100) a = fmaf(vrow[j], wrow[j], a);
    }
    #pragma unroll
    for (int o = 16; o; o >>= 1) a += __shfl_xor_sync(0xffffffffu, a, o);
    if (lane == 0) {
        float bias = which ? fc3_b[e] : fc2_b[e];
        if (which) g_of3[r] = a + bias;
        else       g_of2[r] = a + bias;
    }
}

// ---------------------------------------------------------------------------
// K1b: w2v, w4v, c1, c2 — independent coalesced thread groups, one block
// ---------------------------------------------------------------------------
__global__ __launch_bounds__(1024) void k_pre_b(
        const float* __restrict__ fc1_w, const float* __restrict__ fc1_b,
        const float* __restrict__ fc4_w, const float* __restrict__ fc4_b) {
    __shared__ float of2s[300], of3s[300], fbs[100];
    int tid = threadIdx.x;
    if (tid < 300) of2s[tid] = g_of2[tid];
    else if (tid < 600) of3s[tid - 300] = g_of3[tid - 300];
    else if (tid < 700) fbs[tid - 600] = fc1_b[tid - 600];
    __syncthreads();

    if (tid < 100) {                 // w2v for column j = tid
        float a0 = 0.f, a1 = 0.f, a2 = 0.f;
        #pragma unroll 4
        for (int e = 0; e < 100; e++) {
            float wv = fc1_w[e * 100 + tid];      // coalesced across j
            a0 = fmaf(of2s[e], wv, a0);
            a1 = fmaf(of2s[100 + e], wv, a1);
            a2 = fmaf(of2s[200 + e], wv, a2);
        }
        g_w2vT[tid] = make_float4(a0, a1, a2, 0.f);
    } else if (tid >= 128 && tid < 428) {        // w4v
        int d = tid - 128;
        int v = d / 100, j = d % 100;
        float a = 0.f;
        #pragma unroll 4
        for (int e = 0; e < 100; e++)
            a = fmaf(of3s[v * 100 + e], fc4_w[e * 100 + j], a);
        g_w4v[d] = a;
    } else if (tid >= 512 && tid < 515) {        // c1
        int v = tid - 512;
        float a = 0.f;
        for (int e = 0; e < 100; e++) a = fmaf(of2s[v * 100 + e], fbs[e], a);
        g_c1[v] = a;
    } else if (tid >= 516 && tid < 519) {        // c2
        int v = tid - 516;
        float a = 0.f;
        for (int e = 0; e < 100; e++) a = fmaf(of3s[v * 100 + e], fc4_b[e], a);
        g_c2[v] = a;
    }
}

// ---------------------------------------------------------------------------
// K2: stage 1 — warp-centric, x rows held in registers, no smem staging.
// Warp w owns rows s = w, w+8, ... (13 rows for w<4, 12 for w>=4).
// Lane covers e-columns [4*lane, 4*lane+4) (lanes 25..31 zero).
// All shuffles unconditional (invalid iterations contribute zeros).
// ---------------------------------------------------------------------------
__global__ __launch_bounds__(256) void k_stage1(const float* __restrict__ x) {
    __shared__ __align__(16) float pm[100 * 4];   // m1 -> p=exp(m-mx), [s][4]
    __shared__ float part[8 * 300];               // per-warp Y partials [w][k][25]
    __shared__ float red[8];                      // max[0..2], invsum[4..6]
    int tid = threadIdx.x;
    int w = tid >> 5;
    int lane = tid & 31;
    int b = blockIdx.x;
    const float4* xb = (const float4*)(x + (size_t)b * 10000);  // row s at s*25

    // Per-lane weight columns: w2vT[4*lane + c]
    float4 wj[4];
    #pragma unroll
    for (int k = 0; k < 4; k++)
        wj[k] = (lane < 25) ? g_w2vT[lane * 4 + k] : make_float4(0.f, 0.f, 0.f, 0.f);

    int nr = (w < 4) ? 13 : 12;

    // Load this warp's rows into registers (deep MLP); invalid slots zero.
    float4 xr[13];
    #pragma unroll
    for (int r = 0; r < 13; r++) {
        if (r < nr && lane < 25) xr[r] = xb[(w + r * 8) * 25 + lane];
        else xr[r] = make_float4(0.f, 0.f, 0.f, 0.f);
    }

    // Pass 1: m1 dots + |x| mask. Shuffle reduce every iteration, all lanes.
    #pragma unroll
    for (int r = 0; r < 13; r++) {
        float4 xv = xr[r];
        float sa = fabsf(xv.x) + fabsf(xv.y) + fabsf(xv.z) + fabsf(xv.w);
        float a0 = xv.x * wj[0].x; a0 = fmaf(xv.y, wj[1].x, a0);
        a0 = fmaf(xv.z, wj[2].x, a0); a0 = fmaf(xv.w, wj[3].x, a0);
        float a1 = xv.x * wj[0].y; a1 = fmaf(xv.y, wj[1].y, a1);
        a1 = fmaf(xv.z, wj[2].y, a1); a1 = fmaf(xv.w, wj[3].y, a1);
        float a2 = xv.x * wj[0].z; a2 = fmaf(xv.y, wj[1].z, a2);
        a2 = fmaf(xv.z, wj[2].z, a2); a2 = fmaf(xv.w, wj[3].z, a2);
        #pragma unroll
        for (int o = 16; o; o >>= 1) {
            a0 += __shfl_xor_sync(0xffffffffu, a0, o);
            a1 += __shfl_xor_sync(0xffffffffu, a1, o);
            a2 += __shfl_xor_sync(0xffffffffu, a2, o);
            sa += __shfl_xor_sync(0xffffffffu, sa, o);
        }
        if (lane == 0 && r < nr) {
            int s = w + r * 8;
            float m0 = (a0 + g_c1[0]) * SCALE;
            float m1 = (a1 + g_c1[1]) * SCALE;
            float m2 = (a2 + g_c1[2]) * SCALE;
            if (sa == 0.0f) { m0 = PADV; m1 = PADV; m2 = PADV; }
            float* o_ = &pm[s * 4];
            o_[0] = m0; o_[1] = m1; o_[2] = m2; o_[3] = 0.f;
        }
    }
    __syncthreads();

    // Per-v softmax stats over S=100 (warps 0..2, whole warps participate)
    if (tid < 96) {
        int v = tid >> 5;
        int ln = tid & 31;
        float vals[4];
        float mx = NEGBIG;
        #pragma unroll
        for (int i = 0; i < 4; i++) {
            int s = ln + i * 32;
            vals[i] = (s < 100) ? pm[s * 4 + v] : NEGBIG;
            mx = fmaxf(mx, vals[i]);
        }
        #pragma unroll
        for (int o = 16; o; o >>= 1) mx = fmaxf(mx, __shfl_xor_sync(0xffffffffu, mx, o));
        float sum = 0.f;
        #pragma unroll
        for (int i = 0; i < 4; i++) {
            int s = ln + i * 32;
            if (s < 100) sum += __expf(vals[i] - mx);
        }
        #pragma unroll
        for (int o = 16; o; o >>= 1) sum += __shfl_xor_sync(0xffffffffu, sum, o);
        if (ln == 0) { red[v] = mx; red[4 + v] = 1.0f / sum; }
    }
    __syncthreads();

    // p = exp(m - mx) (unnormalized; invsum folded into final Y scale)
    if (tid < 100) {
        float* o_ = &pm[tid * 4];
        o_[0] = __expf(o_[0] - red[0]);
        o_[1] = __expf(o_[1] - red[1]);
        o_[2] = __expf(o_[2] - red[2]);
    }
    __syncthreads();

    // Pass 2: Y accumulation from register-resident rows (no shuffles)
    float4 c0 = make_float4(0.f, 0.f, 0.f, 0.f);
    float4 c1v = make_float4(0.f, 0.f, 0.f, 0.f);
    float4 c2v = make_float4(0.f, 0.f, 0.f, 0.f);
    #pragma unroll
    for (int r = 0; r < 13; r++) {
        if (r < nr) {
            int s = w + r * 8;
            float4 p = *(const float4*)&pm[s * 4];   // warp-broadcast
            float4 xv = xr[r];
            c0.x = fmaf(p.x, xv.x, c0.x); c0.y = fmaf(p.x, xv.y, c0.y);
            c0.z = fmaf(p.x, xv.z, c0.z); c0.w = fmaf(p.x, xv.w, c0.w);
            c1v.x = fmaf(p.y, xv.x, c1v.x); c1v.y = fmaf(p.y, xv.y, c1v.y);
            c1v.z = fmaf(p.y, xv.z, c1v.z); c1v.w = fmaf(p.y, xv.w, c1v.w);
            c2v.x = fmaf(p.z, xv.x, c2v.x); c2v.y = fmaf(p.z, xv.y, c2v.y);
            c2v.z = fmaf(p.z, xv.z, c2v.z); c2v.w = fmaf(p.z, xv.w, c2v.w);
        }
    }
    if (lane < 25) {
        float vals[12] = {c0.x, c0.y, c0.z, c0.w,
                          c1v.x, c1v.y, c1v.z, c1v.w,
                          c2v.x, c2v.y, c2v.z, c2v.w};
        #pragma unroll
        for (int k = 0; k < 12; k++) part[w * 300 + k * 25 + lane] = vals[k];
    }
    __syncthreads();

    // Cross-warp reduce + invsum scale, store Y[b][v][e] (v-major, coalesced).
    // Strided loop: 300 outputs across 256 threads (fixes R12 coverage bug).
    for (int i = tid; i < 300; i += 256) {
        int v = i / 100, e = i % 100;
        int le = e >> 2, c = e & 3;
        int k = v * 4 + c;
        float a = 0.f;
        #pragma unroll
        for (int ww = 0; ww < 8; ww++) a += part[ww * 300 + k * 25 + le];
        g_Y[(size_t)b * 300 + i] = a * red[4 + v];
    }
}

// ---------------------------------------------------------------------------
// K3: stage 2 — ws1 mini-GEMM (f32x2 packed) + m2 softmax + output dot
// ---------------------------------------------------------------------------
__global__ __launch_bounds__(128) void k_stage2(const float* __restrict__ tag,
                                                const float* __restrict__ fc1_w,
                                                const float* __restrict__ fc1_b,
                                                float* __restrict__ out) {
    extern __shared__ __align__(16) float smem[];
    float* fws  = smem;              // 10200
    float* ysT2 = fws + 10200;       // 2400
    float* ws1s = ysT2 + 2400;       // 2400
    float* tgA  = ws1s + 2400;       // 8000
    float* w4vs = tgA + 8000;        // 300
    float* fb   = w4vs + 300;        // 100
    float* c2s  = fb + 100;          // 4
    float* m2s  = c2s + 4;           // 240
    float* dss  = m2s + 240;         // 240
    float* red2 = dss + 240;         // 48

    int tid = threadIdx.x;
    int b0 = blockIdx.x * GB;

    // fc1_w -> padded smem rows (stride 102 keeps float2 loads 8B aligned)
    const float4* fw4 = (const float4*)fc1_w;
    #pragma unroll 5
    for (int i = tid; i < 2500; i += 128) {
        float4 w = fw4[i];
        int e = i / 25, c = (i % 25) * 4;
        float* r = &fws[e * 102 + c];
        r[0] = w.x; r[1] = w.y; r[2] = w.z; r[3] = w.w;
    }
    // tags (contiguous copy)
    const float4* tp = (const float4*)(tag + (size_t)b0 * 1000);
    #pragma unroll 4
    for (int i = tid; i < GB * 250; i += 128) ((float4*)tgA)[i] = tp[i];
    // Y -> pair-transposed layout
    for (int i = tid; i < 1200; i += 128) {
        int g = i / 150, r = i % 150, v = r / 50, jp = r % 50;
        float2 val = *(const float2*)(g_Y + (size_t)(b0 + g) * 300 + v * 100 + jp * 2);
        float* dst = &ysT2[jp * 48 + (g * 3 + v) * 2];
        dst[0] = val.x; dst[1] = val.y;
    }
    for (int i = tid; i < 300; i += 128) w4vs[i] = g_w4v[i];
    if (tid < 100) fb[tid] = fc1_b[tid];
    if (tid < 3)   c2s[tid] = g_c2[tid];
    __syncthreads();

    // ws1[g][v][e] = sum_j Y[g][v][j] * fc1_w[e][j] + fc1_b[e]
    if (tid < 100) {
        unsigned long long acc[24];
        #pragma unroll
        for (int k = 0; k < 24; k++) acc[k] = 0ull;
        const float* fr = &fws[tid * 102];
        #pragma unroll 2
        for (int jp = 0; jp < 50; jp++) {
            unsigned long long w2 = *(const unsigned long long*)(fr + jp * 2);
            const ulonglong2* yr = (const ulonglong2*)&ysT2[jp * 48];
            #pragma unroll
            for (int p = 0; p < 12; p++) {
                ulonglong2 y = yr[p];
                asm("fma.rn.f32x2 %0, %1, %2, %0;" : "+l"(acc[2 * p])     : "l"(w2), "l"(y.x));
                asm("fma.rn.f32x2 %0, %1, %2, %0;" : "+l"(acc[2 * p + 1]) : "l"(w2), "l"(y.y));
            }
        }
        float bias = fb[tid];
        #pragma unroll
        for (int k = 0; k < 24; k++) {
            union { unsigned long long u; float2 f; } cv;
            cv.u = acc[k];
            ws1s[k * 100 + tid] = cv.f.x + cv.f.y + bias;
        }
    }
    __syncthreads();

    // m2[g][t][v] and d[g][t][v] dots — 240 triples across 128 threads
    for (int i = tid; i < 240; i += 128) {
        int g = i / 30, r = i % 30, t = r / 3, v = r % 3;
        const float* tr = &tgA[g * 1000 + t * 100];
        const float* wr = &w4vs[v * 100];
        const float* sr = &ws1s[(g * 3 + v) * 100];
        float am = 0.f, ad = 0.f;
        #pragma unroll 4
        for (int e = 0; e < 100; e++) {
            float te = tr[e];
            am = fmaf(te, wr[e], am);
            ad = fmaf(te, sr[e], ad);
        }
        m2s[i] = (am + c2s[v]) * SCALE;
        dss[i] = ad;
    }
    __syncthreads();

    // softmax over T per (g,v)
    if (tid < 24) {
        int g = tid / 3, v = tid % 3;
        float mx = NEGBIG;
        #pragma unroll
        for (int t = 0; t < 10; t++) mx = fmaxf(mx, m2s[g * 30 + t * 3 + v]);
        float s = 0.f;
        #pragma unroll
        for (int t = 0; t < 10; t++) s += __expf(m2s[g * 30 + t * 3 + v] - mx);
        red2[tid] = mx;
        red2[24 + tid] = 1.0f / s;
    }
    __syncthreads();

    // out[b][t] = sum_v sm2[t][v] * d[t][v]
    if (tid < 80) {
        int g = tid / 10, t = tid % 10;
        float o = 0.f;
        #pragma unroll
        for (int v = 0; v < 3; v++) {
            float w = __expf(m2s[g * 30 + t * 3 + v] - red2[g * 3 + v]) * red2[24 + g * 3 + v];
            o = fmaf(w, dss[g * 30 + t * 3 + v], o);
        }
        out[(size_t)(b0 + g) * 10 + t] = o;
    }
}

// ---------------------------------------------------------------------------
extern "C" void kernel_launch(void* const* d_in, const int* in_sizes, int n_in,
                              void* d_out, int out_size) {
    const float* x     = (const float*)d_in[0];
    const float* tag   = (const float*)d_in[1];
    const float* vk    = (const float*)d_in[2];
    const float* fc1_w = (const float*)d_in[3];
    const float* fc1_b = (const float*)d_in[4];
    const float* fc2_w = (const float*)d_in[5];
    const float* fc2_b = (const float*)d_in[6];
    const float* fc3_w = (const float*)d_in[7];
    const float* fc3_b = (const float*)d_in[8];
    const float* fc4_w = (const float*)d_in[9];
    const float* fc4_b = (const float*)d_in[10];
    float* out = (float*)d_out;

    const int SMEM2 = (10200 + 2400 + 2400 + 8000 + 300 + 100 + 4 + 240 + 240 + 48) * 4;
    cudaFuncSetAttribute(k_stage2, cudaFuncAttributeMaxDynamicSharedMemorySize, SMEM2);

    k_pre_a<<<75, 256>>>(vk, fc2_w, fc2_b, fc3_w, fc3_b);
    k_pre_b<<<1, 1024>>>(fc1_w, fc1_b, fc4_w, fc4_b);
    k_stage1<<<8192, 256>>>(x);
    k_stage2<<<8192 / GB, 128, SMEM2>>>(tag, fc1_w, fc1_b, out);
}

// round 16
// speedup vs baseline: 1.2100x; 1.0682x over previous
#include <cuda_runtime.h>
#include <math.h>

// MVKE collapsed-algebra implementation, cp.async pipelined.
// B=8192, S=100, T=10, E=100, V=3, all fp32.
#define SCALE 0.1f
#define PADV  (-4294967295.0f)
#define NEGBIG (-3.402823466e38f)
#define GB 8                      // batches per stage-2 block
#define NB 4                      // batches per stage-1 block
#define XST 102                   // stage-1 smem row stride (floats, 8B-aligned rows)

// Precomputed small tensors + scratch
__device__ float4 g_w2vT[100];          // (w2v[0][j], w2v[1][j], w2v[2][j], 0)
__device__ float  g_c1[4];
__device__ float  g_w4v[3 * 100];       // [v][j]
__device__ float  g_c2[4];
__device__ float  g_of2[300];           // of2[v][e]
__device__ float  g_of3[300];           // of3[v][e]
__device__ float  g_Y[8192 * 300];      // Y[b][v][e]

// ---------------- cp.async helpers ----------------
__device__ __forceinline__ unsigned smem_u32(const void* p) {
    return (unsigned)__cvta_generic_to_shared(p);
}
__device__ __forceinline__ void cpa8(unsigned dst, const void* src) {
    asm volatile("cp.async.ca.shared.global [%0], [%1], 8;" :: "r"(dst), "l"(src));
}
__device__ __forceinline__ void cpa16(unsigned dst, const void* src) {
    asm volatile("cp.async.cg.shared.global [%0], [%1], 16;" :: "r"(dst), "l"(src));
}
#define CPA_COMMIT() asm volatile("cp.async.commit_group;")
#define CPA_WAIT(n)  asm volatile("cp.async.wait_group %0;" :: "n"(n))

// ---------------------------------------------------------------------------
// K1a: of2/of3 — 600 length-100 dots, one warp each, 75 blocks (600 warps)
// ---------------------------------------------------------------------------
__global__ __launch_bounds__(256) void k_pre_a(
        const float* __restrict__ vk,
        const float* __restrict__ fc2_w, const float* __restrict__ fc2_b,
        const float* __restrict__ fc3_w, const float* __restrict__ fc3_b) {
    int gw = blockIdx.x * 8 + (threadIdx.x >> 5);
    int lane = threadIdx.x & 31;
    int which = gw / 300;
    int r = gw % 300;
    int v = r / 100, e = r % 100;
    const float* W = which ? fc3_w : fc2_w;
    const float* vrow = vk + v * 100;
    const float* wrow = W + e * 100;
    float a = 0.f;
    #pragma unroll
    for (int k = 0; k < 4; k++) {
        int j = lane + k * 32;
        if (j < 100) a = fmaf(vrow[j], wrow[j], a);
    }
    #pragma unroll
    for (int o = 16; o; o >>= 1) a += __shfl_xor_sync(0xffffffffu, a, o);
    if (lane == 0) {
        float bias = which ? fc3_b[e] : fc2_b[e];
        if (which) g_of3[r] = a + bias;
        else       g_of2[r] = a + bias;
    }
}

// ---------------------------------------------------------------------------
// K1b: w2v, w4v, c1, c2 — independent coalesced thread groups, one block
// ---------------------------------------------------------------------------
__global__ __launch_bounds__(1024) void k_pre_b(
        const float* __restrict__ fc1_w, const float* __restrict__ fc1_b,
        const float* __restrict__ fc4_w, const float* __restrict__ fc4_b) {
    __shared__ float of2s[300], of3s[300], fbs[100];
    int tid = threadIdx.x;
    if (tid < 300) of2s[tid] = g_of2[tid];
    else if (tid < 600) of3s[tid - 300] = g_of3[tid - 300];
    else if (tid < 700) fbs[tid - 600] = fc1_b[tid - 600];
    __syncthreads();

    if (tid < 100) {
        float a0 = 0.f, a1 = 0.f, a2 = 0.f;
        #pragma unroll 4
        for (int e = 0; e < 100; e++) {
            float wv = fc1_w[e * 100 + tid];
            a0 = fmaf(of2s[e], wv, a0);
            a1 = fmaf(of2s[100 + e], wv, a1);
            a2 = fmaf(of2s[200 + e], wv, a2);
        }
        g_w2vT[tid] = make_float4(a0, a1, a2, 0.f);
    } else if (tid >= 128 && tid < 428) {
        int d = tid - 128;
        int v = d / 100, j = d % 100;
        float a = 0.f;
        #pragma unroll 4
        for (int e = 0; e < 100; e++)
            a = fmaf(of3s[v * 100 + e], fc4_w[e * 100 + j], a);
        g_w4v[d] = a;
    } else if (tid >= 512 && tid < 515) {
        int v = tid - 512;
        float a = 0.f;
        for (int e = 0; e < 100; e++) a = fmaf(of2s[v * 100 + e], fbs[e], a);
        g_c1[v] = a;
    } else if (tid >= 516 && tid < 519) {
        int v = tid - 516;
        float a = 0.f;
        for (int e = 0; e < 100; e++) a = fmaf(of3s[v * 100 + e], fc4_b[e], a);
        g_c2[v] = a;
    }
}

// ---------------------------------------------------------------------------
// K2: stage 1 — NB batches/block, double-buffered cp.async x tiles.
// Dynamic smem: 2 tiles of 100*XST floats. Compute = split-K (200 threads).
// ---------------------------------------------------------------------------
__global__ __launch_bounds__(256) void k_stage1(const float* __restrict__ x) {
    extern __shared__ __align__(16) float xs2[];   // 2 * 100*XST
    __shared__ __align__(16) float pp[200 * 4];    // split-K partials
    __shared__ __align__(16) float pm[100 * 4];    // m1 -> exp(m-mx)
    __shared__ __align__(16) float4 w2s[100];
    __shared__ float red[8];
    int tid = threadIdx.x;
    int b0 = blockIdx.x * NB;

    if (tid < 100) w2s[tid] = g_w2vT[tid];

    // Prefetch tile 0 into buffer 0
    {
        const float* src = x + (size_t)b0 * 10000;
        float* dst = xs2;
        for (int p = tid; p < 5000; p += 256) {
            int s = p / 50, c = (p % 50) * 2;
            cpa8(smem_u32(dst + s * XST + c), src + p * 2);
        }
        CPA_COMMIT();
    }

    for (int i = 0; i < NB; i++) {
        if (i + 1 < NB) {   // prefetch next tile into the other buffer
            const float* src = x + (size_t)(b0 + i + 1) * 10000;
            float* dst = xs2 + ((i + 1) & 1) * (100 * XST);
            for (int p = tid; p < 5000; p += 256) {
                int s = p / 50, c = (p % 50) * 2;
                cpa8(smem_u32(dst + s * XST + c), src + p * 2);
            }
            CPA_COMMIT();
            CPA_WAIT(1);    // tile i complete, tile i+1 in flight
        } else {
            CPA_WAIT(0);
        }
        __syncthreads();
        const float* xb = xs2 + (i & 1) * (100 * XST);
        int b = b0 + i;

        // pass 1: m1 half-dots (task = (half, s), 50-deep)
        if (tid < 200) {
            int s = tid % 100, h = tid / 100;
            const float* row = xb + s * XST + h * 50;
            const float4* wv = &w2s[h * 50];
            float a0 = 0.f, a1 = 0.f, a2 = 0.f, sa = 0.f;
            #pragma unroll 10
            for (int j = 0; j < 50; j++) {
                float xv = row[j];
                float4 w = wv[j];
                sa += fabsf(xv);
                a0 = fmaf(xv, w.x, a0);
                a1 = fmaf(xv, w.y, a1);
                a2 = fmaf(xv, w.z, a2);
            }
            float* o = &pp[tid * 4];
            o[0] = a0; o[1] = a1; o[2] = a2; o[3] = sa;
        }
        __syncthreads();

        // combine halves -> m1 with zero-row mask
        if (tid < 100) {
            const float* p0 = &pp[tid * 4];
            const float* p1 = &pp[(tid + 100) * 4];
            float sa = p0[3] + p1[3];
            float m0 = (p0[0] + p1[0] + g_c1[0]) * SCALE;
            float m1 = (p0[1] + p1[1] + g_c1[1]) * SCALE;
            float m2 = (p0[2] + p1[2] + g_c1[2]) * SCALE;
            if (sa == 0.0f) { m0 = PADV; m1 = PADV; m2 = PADV; }
            float* o = &pm[tid * 4];
            o[0] = m0; o[1] = m1; o[2] = m2; o[3] = 0.f;
        }
        __syncthreads();

        // per-v softmax stats over S
        if (tid < 96) {
            int v = tid >> 5;
            int ln = tid & 31;
            float vals[4];
            float mx = NEGBIG;
            #pragma unroll
            for (int k = 0; k < 4; k++) {
                int s = ln + k * 32;
                vals[k] = (s < 100) ? pm[s * 4 + v] : NEGBIG;
                mx = fmaxf(mx, vals[k]);
            }
            #pragma unroll
            for (int o = 16; o; o >>= 1) mx = fmaxf(mx, __shfl_xor_sync(0xffffffffu, mx, o));
            float sum = 0.f;
            #pragma unroll
            for (int k = 0; k < 4; k++) {
                int s = ln + k * 32;
                if (s < 100) sum += __expf(vals[k] - mx);
            }
            #pragma unroll
            for (int o = 16; o; o >>= 1) sum += __shfl_xor_sync(0xffffffffu, sum, o);
            if (ln == 0) { red[v] = mx; red[4 + v] = 1.0f / sum; }
        }
        __syncthreads();

        // pm := exp(m - mx)  (invsum folded into final Y scale)
        if (tid < 100) {
            float* o = &pm[tid * 4];
            o[0] = __expf(o[0] - red[0]);
            o[1] = __expf(o[1] - red[1]);
            o[2] = __expf(o[2] - red[2]);
        }
        __syncthreads();

        // pass 2: Y half-sums (task = (half, e), 50 s each)
        if (tid < 200) {
            int e = tid % 100, h = tid / 100;
            float a0 = 0.f, a1 = 0.f, a2 = 0.f;
            #pragma unroll 10
            for (int s = h * 50; s < h * 50 + 50; s++) {
                float xv = xb[s * XST + e];
                float4 w = *(const float4*)&pm[s * 4];   // broadcast
                a0 = fmaf(xv, w.x, a0);
                a1 = fmaf(xv, w.y, a1);
                a2 = fmaf(xv, w.z, a2);
            }
            float* o = &pp[tid * 4];
            o[0] = a0; o[1] = a1; o[2] = a2;
        }
        __syncthreads();

        // combine + invsum scale -> Y[b][v][e]
        for (int k = tid; k < 300; k += 256) {
            int v = k / 100, e = k % 100;
            float a = pp[e * 4 + v] + pp[(e + 100) * 4 + v];
            g_Y[(size_t)b * 300 + k] = a * red[4 + v];
        }
        __syncthreads();   // protects pp/pm/red AND buffer reuse next iteration
    }
}

// ---------------------------------------------------------------------------
// K3: stage 2 — cp.async front-loaded fc1_w + tags; ws1 f32x2 GEMM; epilogue
// ---------------------------------------------------------------------------
__global__ __launch_bounds__(128) void k_stage2(const float* __restrict__ tag,
                                                const float* __restrict__ fc1_w,
                                                const float* __restrict__ fc1_b,
                                                float* __restrict__ out) {
    extern __shared__ __align__(16) float smem[];
    float* fws  = smem;              // 10200  (100 rows, stride 102)
    float* ysT2 = fws + 10200;       // 2400
    float* ws1s = ysT2 + 2400;       // 2400
    float* tgA  = ws1s + 2400;       // 8000
    float* w4vs = tgA + 8000;        // 300
    float* fb   = w4vs + 300;        // 100
    float* c2s  = fb + 100;          // 4
    float* m2s  = c2s + 4;           // 240
    float* dss  = m2s + 240;         // 240
    float* red2 = dss + 240;         // 48

    int tid = threadIdx.x;
    int b0 = blockIdx.x * GB;

    // cp.async: fc1_w -> fws (8B chunks, stride-102 rows) + tags -> tgA (16B)
    for (int p = tid; p < 5000; p += 128) {
        int e = p / 50, c = (p % 50) * 2;
        cpa8(smem_u32(fws + e * 102 + c), fc1_w + p * 2);
    }
    {
        const float* tp = tag + (size_t)b0 * 1000;
        for (int i = tid; i < GB * 250; i += 128)
            cpa16(smem_u32(tgA + i * 4), tp + i * 4);
    }
    CPA_COMMIT();

    // Overlapped manual loads: Y pair-transpose, w4v, fc1_b, c2
    for (int i = tid; i < 1200; i += 128) {
        int g = i / 150, r = i % 150, v = r / 50, jp = r % 50;
        float2 val = *(const float2*)(g_Y + (size_t)(b0 + g) * 300 + v * 100 + jp * 2);
        float* dst = &ysT2[jp * 48 + (g * 3 + v) * 2];
        dst[0] = val.x; dst[1] = val.y;
    }
    for (int i = tid; i < 300; i += 128) w4vs[i] = g_w4v[i];
    if (tid < 100) fb[tid] = fc1_b[tid];
    if (tid < 3)   c2s[tid] = g_c2[tid];
    CPA_WAIT(0);
    __syncthreads();

    // ws1[g][v][e] = sum_j Y[g][v][j] * fc1_w[e][j] + fc1_b[e]
    if (tid < 100) {
        unsigned long long acc[24];
        #pragma unroll
        for (int k = 0; k < 24; k++) acc[k] = 0ull;
        const float* fr = &fws[tid * 102];
        #pragma unroll 2
        for (int jp = 0; jp < 50; jp++) {
            unsigned long long w2 = *(const unsigned long long*)(fr + jp * 2);
            const ulonglong2* yr = (const ulonglong2*)&ysT2[jp * 48];
            #pragma unroll
            for (int p = 0; p < 12; p++) {
                ulonglong2 y = yr[p];
                asm("fma.rn.f32x2 %0, %1, %2, %0;" : "+l"(acc[2 * p])     : "l"(w2), "l"(y.x));
                asm("fma.rn.f32x2 %0, %1, %2, %0;" : "+l"(acc[2 * p + 1]) : "l"(w2), "l"(y.y));
            }
        }
        float bias = fb[tid];
        #pragma unroll
        for (int k = 0; k < 24; k++) {
            union { unsigned long long u; float2 f; } cv;
            cv.u = acc[k];
            ws1s[k * 100 + tid] = cv.f.x + cv.f.y + bias;
        }
    }
    __syncthreads();

    // m2[g][t][v] and d[g][t][v] dots — 240 triples across 128 threads
    for (int i = tid; i < 240; i += 128) {
        int g = i / 30, r = i % 30, t = r / 3, v = r % 3;
        const float* tr = &tgA[g * 1000 + t * 100];
        const float* wr = &w4vs[v * 100];
        const float* sr = &ws1s[(g * 3 + v) * 100];
        float am = 0.f, ad = 0.f;
        #pragma unroll 4
        for (int e = 0; e < 100; e++) {
            float te = tr[e];
            am = fmaf(te, wr[e], am);
            ad = fmaf(te, sr[e], ad);
        }
        m2s[i] = (am + c2s[v]) * SCALE;
        dss[i] = ad;
    }
    __syncthreads();

    // softmax over T per (g,v)
    if (tid < 24) {
        int g = tid / 3, v = tid % 3;
        float mx = NEGBIG;
        #pragma unroll
        for (int t = 0; t < 10; t++) mx = fmaxf(mx, m2s[g * 30 + t * 3 + v]);
        float s = 0.f;
        #pragma unroll
        for (int t = 0; t < 10; t++) s += __expf(m2s[g * 30 + t * 3 + v] - mx);
        red2[tid] = mx;
        red2[24 + tid] = 1.0f / s;
    }
    __syncthreads();

    // out[b][t] = sum_v sm2[t][v] * d[t][v]
    if (tid < 80) {
        int g = tid / 10, t = tid % 10;
        float o = 0.f;
        #pragma unroll
        for (int v = 0; v < 3; v++) {
            float w = __expf(m2s[g * 30 + t * 3 + v] - red2[g * 3 + v]) * red2[24 + g * 3 + v];
            o = fmaf(w, dss[g * 30 + t * 3 + v], o);
        }
        out[(size_t)(b0 + g) * 10 + t] = o;
    }
}

// ---------------------------------------------------------------------------
extern "C" void kernel_launch(void* const* d_in, const int* in_sizes, int n_in,
                              void* d_out, int out_size) {
    const float* x     = (const float*)d_in[0];
    const float* tag   = (const float*)d_in[1];
    const float* vk    = (const float*)d_in[2];
    const float* fc1_w = (const float*)d_in[3];
    const float* fc1_b = (const float*)d_in[4];
    const float* fc2_w = (const float*)d_in[5];
    const float* fc2_b = (const float*)d_in[6];
    const float* fc3_w = (const float*)d_in[7];
    const float* fc3_b = (const float*)d_in[8];
    const float* fc4_w = (const float*)d_in[9];
    const float* fc4_b = (const float*)d_in[10];
    float* out = (float*)d_out;

    const int SMEM1 = 2 * 100 * XST * 4;   // 81600 B
    const int SMEM2 = (10200 + 2400 + 2400 + 8000 + 300 + 100 + 4 + 240 + 240 + 48) * 4;
    cudaFuncSetAttribute(k_stage1, cudaFuncAttributeMaxDynamicSharedMemorySize, SMEM1);
    cudaFuncSetAttribute(k_stage2, cudaFuncAttributeMaxDynamicSharedMemorySize, SMEM2);

    k_pre_a<<<75, 256>>>(vk, fc2_w, fc2_b, fc3_w, fc3_b);
    k_pre_b<<<1, 1024>>>(fc1_w, fc1_b, fc4_w, fc4_b);
    k_stage1<<<8192 / NB, 256, SMEM1>>>(x);
    k_stage2<<<8192 / GB, 128, SMEM2>>>(tag, fc1_w, fc1_b, out);
}

// round 17
// speedup vs baseline: 1.3212x; 1.0920x over previous
#include <cuda_runtime.h>
#include <math.h>

// MVKE collapsed-algebra implementation, f32x2-packed + occupancy-tuned.
// B=8192, S=100, T=10, E=100, V=3, all fp32.
#define SCALE 0.1f
#define PADV  (-4294967295.0f)
#define NEGBIG (-3.402823466e38f)
#define GB 8                      // batches per stage-2 block
#define NB 4                      // batches per stage-1 block
#define XST 106                   // stage-1 smem row stride (floats; 8B rows, bank-clean)

typedef unsigned long long ull;

// Precomputed small tensors + scratch
__device__ float4 g_w2vT[100];          // (w2v[0][j], w2v[1][j], w2v[2][j], 0)
__device__ float  g_c1[4];
__device__ float  g_w4v[3 * 100];       // [v][j]
__device__ float  g_c2[4];
__device__ float  g_of2[300];           // of2[v][e]
__device__ float  g_of3[300];           // of3[v][e]
__device__ float  g_Y[8192 * 300];      // Y[b][v][e]

// ---------------- helpers ----------------
__device__ __forceinline__ unsigned smem_u32(const void* p) {
    return (unsigned)__cvta_generic_to_shared(p);
}
__device__ __forceinline__ void cpa8(unsigned dst, const void* src) {
    asm volatile("cp.async.ca.shared.global [%0], [%1], 8;" :: "r"(dst), "l"(src));
}
#define CPA_COMMIT() asm volatile("cp.async.commit_group;")
#define CPA_WAIT(n)  asm volatile("cp.async.wait_group %0;" :: "n"(n))

__device__ __forceinline__ void fma2(ull& acc, ull a, ull b) {
    asm("fma.rn.f32x2 %0, %1, %2, %0;" : "+l"(acc) : "l"(a), "l"(b));
}
__device__ __forceinline__ void add2(ull& acc, ull a) {
    asm("add.rn.f32x2 %0, %1, %2;" : "=l"(acc) : "l"(acc), "l"(a));
}
__device__ __forceinline__ ull pack2(float lo, float hi) {
    ull r; asm("mov.b64 %0, {%1, %2};" : "=l"(r) : "f"(lo), "f"(hi)); return r;
}
__device__ __forceinline__ float hsum2(ull a) {
    union { ull u; float2 f; } c; c.u = a; return c.f.x + c.f.y;
}

// ---------------------------------------------------------------------------
// K1a: of2/of3 — 600 length-100 dots, one warp each, 75 blocks (600 warps)
// ---------------------------------------------------------------------------
__global__ __launch_bounds__(256) void k_pre_a(
        const float* __restrict__ vk,
        const float* __restrict__ fc2_w, const float* __restrict__ fc2_b,
        const float* __restrict__ fc3_w, const float* __restrict__ fc3_b) {
    int gw = blockIdx.x * 8 + (threadIdx.x >> 5);
    int lane = threadIdx.x & 31;
    int which = gw / 300;
    int r = gw % 300;
    int v = r / 100, e = r % 100;
    const float* W = which ? fc3_w : fc2_w;
    const float* vrow = vk + v * 100;
    const float* wrow = W + e * 100;
    float a = 0.f;
    #pragma unroll
    for (int k = 0; k < 4; k++) {
        int j = lane + k * 32;
        if (j < 100) a = fmaf(vrow[j], wrow[j], a);
    }
    #pragma unroll
    for (int o = 16; o; o >>= 1) a += __shfl_xor_sync(0xffffffffu, a, o);
    if (lane == 0) {
        float bias = which ? fc3_b[e] : fc2_b[e];
        if (which) g_of3[r] = a + bias;
        else       g_of2[r] = a + bias;
    }
}

// ---------------------------------------------------------------------------
// K1b: w2v, w4v, c1, c2 — independent coalesced thread groups, one block
// ---------------------------------------------------------------------------
__global__ __launch_bounds__(1024) void k_pre_b(
        const float* __restrict__ fc1_w, const float* __restrict__ fc1_b,
        const float* __restrict__ fc4_w, const float* __restrict__ fc4_b) {
    __shared__ float of2s[300], of3s[300], fbs[100];
    int tid = threadIdx.x;
    if (tid < 300) of2s[tid] = g_of2[tid];
    else if (tid < 600) of3s[tid - 300] = g_of3[tid - 300];
    else if (tid < 700) fbs[tid - 600] = fc1_b[tid - 600];
    __syncthreads();

    if (tid < 100) {
        float a0 = 0.f, a1 = 0.f, a2 = 0.f;
        #pragma unroll 4
        for (int e = 0; e < 100; e++) {
            float wv = fc1_w[e * 100 + tid];
            a0 = fmaf(of2s[e], wv, a0);
            a1 = fmaf(of2s[100 + e], wv, a1);
            a2 = fmaf(of2s[200 + e], wv, a2);
        }
        g_w2vT[tid] = make_float4(a0, a1, a2, 0.f);
    } else if (tid >= 128 && tid < 428) {
        int d = tid - 128;
        int v = d / 100, j = d % 100;
        float a = 0.f;
        #pragma unroll 4
        for (int e = 0; e < 100; e++)
            a = fmaf(of3s[v * 100 + e], fc4_w[e * 100 + j], a);
        g_w4v[d] = a;
    } else if (tid >= 512 && tid < 515) {
        int v = tid - 512;
        float a = 0.f;
        for (int e = 0; e < 100; e++) a = fmaf(of2s[v * 100 + e], fbs[e], a);
        g_c1[v] = a;
    } else if (tid >= 516 && tid < 519) {
        int v = tid - 516;
        float a = 0.f;
        for (int e = 0; e < 100; e++) a = fmaf(of3s[v * 100 + e], fc4_b[e], a);
        g_c2[v] = a;
    }
}

// ---------------------------------------------------------------------------
// K2: stage 1 — NB batches/block, double-buffered cp.async, f32x2 compute.
// ---------------------------------------------------------------------------
__global__ __launch_bounds__(256) void k_stage1(const float* __restrict__ x) {
    extern __shared__ __align__(16) float xs2[];   // 2 * 100*XST
    __shared__ __align__(16) float pp[200 * 6];    // split partials
    __shared__ __align__(16) float pm[100 * 4];    // m1 logits
    __shared__ __align__(16) ull   pmd[300];       // exp weights, duplicated pairs
    __shared__ __align__(8)  float2 w2p[152];      // packed w2v pairs [v*50+jp]
    __shared__ float red[8];
    int tid = threadIdx.x;
    int b0 = blockIdx.x * NB;

    // Build packed weight pairs
    if (tid < 150) {
        int v = tid / 50, jp = tid % 50;
        float4 a = g_w2vT[2 * jp], b = g_w2vT[2 * jp + 1];
        float lo = (v == 0) ? a.x : (v == 1) ? a.y : a.z;
        float hi = (v == 0) ? b.x : (v == 1) ? b.y : b.z;
        w2p[v * 50 + jp] = make_float2(lo, hi);
    }

    // Prefetch tile 0
    {
        const float* src = x + (size_t)b0 * 10000;
        for (int p = tid; p < 5000; p += 256) {
            int s = p / 50, c = (p % 50) * 2;
            cpa8(smem_u32(xs2 + s * XST + c), src + p * 2);
        }
        CPA_COMMIT();
    }

    for (int i = 0; i < NB; i++) {
        if (i + 1 < NB) {
            const float* src = x + (size_t)(b0 + i + 1) * 10000;
            float* dst = xs2 + ((i + 1) & 1) * (100 * XST);
            for (int p = tid; p < 5000; p += 256) {
                int s = p / 50, c = (p % 50) * 2;
                cpa8(smem_u32(dst + s * XST + c), src + p * 2);
            }
            CPA_COMMIT();
            CPA_WAIT(1);
        } else {
            CPA_WAIT(0);
        }
        __syncthreads();
        const float* xb = xs2 + (i & 1) * (100 * XST);
        int b = b0 + i;

        // pass 1: packed half-dots. task = (half h, row s), 25 pairs each.
        if (tid < 200) {
            int s = tid % 100, h = tid / 100;
            const ull* row = (const ull*)(xb + s * XST);
            ull acc0 = 0, acc1 = 0, acc2 = 0, sa2 = 0;
            #pragma unroll
            for (int k = 0; k < 25; k++) {
                int jp = h * 25 + k;
                ull x2 = row[jp];
                ull w0 = *(const ull*)&w2p[jp];
                ull w1 = *(const ull*)&w2p[50 + jp];
                ull w2 = *(const ull*)&w2p[100 + jp];
                fma2(acc0, x2, w0);
                fma2(acc1, x2, w1);
                fma2(acc2, x2, w2);
                add2(sa2, x2 & 0x7fffffff7fffffffULL);
            }
            float* o = &pp[tid * 6];
            o[0] = hsum2(acc0); o[1] = hsum2(acc1);
            o[2] = hsum2(acc2); o[3] = hsum2(sa2);
        }
        __syncthreads();

        // combine halves -> m1 with zero-row mask
        if (tid < 100) {
            const float* p0 = &pp[tid * 6];
            const float* p1 = &pp[(tid + 100) * 6];
            float sa = p0[3] + p1[3];
            float m0 = (p0[0] + p1[0] + g_c1[0]) * SCALE;
            float m1 = (p0[1] + p1[1] + g_c1[1]) * SCALE;
            float m2 = (p0[2] + p1[2] + g_c1[2]) * SCALE;
            if (sa == 0.0f) { m0 = PADV; m1 = PADV; m2 = PADV; }
            float* o = &pm[tid * 4];
            o[0] = m0; o[1] = m1; o[2] = m2; o[3] = 0.f;
        }
        __syncthreads();

        // per-v softmax stats over S
        if (tid < 96) {
            int v = tid >> 5;
            int ln = tid & 31;
            float vals[4];
            float mx = NEGBIG;
            #pragma unroll
            for (int k = 0; k < 4; k++) {
                int s = ln + k * 32;
                vals[k] = (s < 100) ? pm[s * 4 + v] : NEGBIG;
                mx = fmaxf(mx, vals[k]);
            }
            #pragma unroll
            for (int o = 16; o; o >>= 1) mx = fmaxf(mx, __shfl_xor_sync(0xffffffffu, mx, o));
            float sum = 0.f;
            #pragma unroll
            for (int k = 0; k < 4; k++) {
                int s = ln + k * 32;
                if (s < 100) sum += __expf(vals[k] - mx);
            }
            #pragma unroll
            for (int o = 16; o; o >>= 1) sum += __shfl_xor_sync(0xffffffffu, sum, o);
            if (ln == 0) { red[v] = mx; red[4 + v] = 1.0f / sum; }
        }
        __syncthreads();

        // pmd[s][v] := (e,e) duplicated packed exp weights
        if (tid < 100) {
            const float* o = &pm[tid * 4];
            float e0 = __expf(o[0] - red[0]);
            float e1 = __expf(o[1] - red[1]);
            float e2 = __expf(o[2] - red[2]);
            pmd[tid * 3 + 0] = pack2(e0, e0);
            pmd[tid * 3 + 1] = pack2(e1, e1);
            pmd[tid * 3 + 2] = pack2(e2, e2);
        }
        __syncthreads();

        // pass 2: Y e-pair sums. task = (quarter q, e-pair ep), 25 s each.
        if (tid < 200) {
            int ep = tid % 50, q = tid / 50;
            ull av0 = 0, av1 = 0, av2 = 0;
            int s0 = q * 25;
            #pragma unroll
            for (int k = 0; k < 25; k++) {
                int s = s0 + k;
                ull x2 = *(const ull*)(xb + s * XST + 2 * ep);
                fma2(av0, x2, pmd[s * 3 + 0]);
                fma2(av1, x2, pmd[s * 3 + 1]);
                fma2(av2, x2, pmd[s * 3 + 2]);
            }
            union { ull u; float2 f; } c0, c1, c2;
            c0.u = av0; c1.u = av1; c2.u = av2;
            float* o = &pp[tid * 6];
            o[0] = c0.f.x; o[1] = c0.f.y;
            o[2] = c1.f.x; o[3] = c1.f.y;
            o[4] = c2.f.x; o[5] = c2.f.y;
        }
        __syncthreads();

        // combine quarters + invsum scale -> Y[b][v][e]
        for (int k = tid; k < 300; k += 256) {
            int v = k / 100, e = k % 100;
            int ep = e >> 1, hf = e & 1;
            float a = 0.f;
            #pragma unroll
            for (int q = 0; q < 4; q++) a += pp[(q * 50 + ep) * 6 + v * 2 + hf];
            g_Y[(size_t)b * 300 + k] = a * red[4 + v];
        }
        __syncthreads();
    }
}

// ---------------------------------------------------------------------------
// K3: stage 2 — 256 thr, no tag staging (64 KB smem -> 3 CTA/SM)
// ---------------------------------------------------------------------------
__global__ __launch_bounds__(256) void k_stage2(const float* __restrict__ tag,
                                                const float* __restrict__ fc1_w,
                                                const float* __restrict__ fc1_b,
                                                float* __restrict__ out) {
    extern __shared__ __align__(16) float smem[];
    float* fws  = smem;              // 10600  (100 rows, stride 106)
    float* ysT2 = fws + 10600;       // 2400
    float* ws1s = ysT2 + 2400;       // 2400
    float* w4vs = ws1s + 2400;       // 300
    float* fb   = w4vs + 300;        // 100
    float* c2s  = fb + 100;          // 4
    float* m2s  = c2s + 4;           // 240
    float* dss  = m2s + 240;         // 240
    float* red2 = dss + 240;         // 48

    int tid = threadIdx.x;
    int b0 = blockIdx.x * GB;

    // cp.async fc1_w -> fws (8B chunks, stride-106 rows)
    for (int p = tid; p < 5000; p += 256) {
        int e = p / 50, c = (p % 50) * 2;
        cpa8(smem_u32(fws + e * 106 + c), fc1_w + p * 2);
    }
    CPA_COMMIT();

    // Overlapped: Y pair-transpose, w4v, fc1_b, c2
    for (int i = tid; i < 1200; i += 256) {
        int g = i / 150, r = i % 150, v = r / 50, jp = r % 50;
        float2 val = *(const float2*)(g_Y + (size_t)(b0 + g) * 300 + v * 100 + jp * 2);
        float* dst = &ysT2[jp * 48 + (g * 3 + v) * 2];
        dst[0] = val.x; dst[1] = val.y;
    }
    for (int i = tid; i < 300; i += 256) w4vs[i] = g_w4v[i];
    if (tid < 100) fb[tid] = fc1_b[tid];
    if (tid < 3)   c2s[tid] = g_c2[tid];
    CPA_WAIT(0);
    __syncthreads();

    // ws1[g][v][e] = sum_j Y[g][v][j] * fc1_w[e][j] + fc1_b[e]
    if (tid < 100) {
        ull acc[24];
        #pragma unroll
        for (int k = 0; k < 24; k++) acc[k] = 0ull;
        const float* fr = &fws[tid * 106];
        #pragma unroll 2
        for (int jp = 0; jp < 50; jp++) {
            ull w2 = *(const ull*)(fr + jp * 2);
            const ulonglong2* yr = (const ulonglong2*)&ysT2[jp * 48];
            #pragma unroll
            for (int p = 0; p < 12; p++) {
                ulonglong2 y = yr[p];
                fma2(acc[2 * p], w2, y.x);
                fma2(acc[2 * p + 1], w2, y.y);
            }
        }
        float bias = fb[tid];
        #pragma unroll
        for (int k = 0; k < 24; k++)
            ws1s[k * 100 + tid] = hsum2(acc[k]) + bias;
    }
    __syncthreads();

    // m2 and d dots — 240 triples, tags straight from global (float4, L1)
    if (tid < 240) {
        int g = tid / 30, r = tid % 30, t = r / 3, v = r % 3;
        const float4* tr = (const float4*)(tag + (size_t)(b0 + g) * 1000 + t * 100);
        const float4* wr = (const float4*)(w4vs + v * 100);
        const float4* sr = (const float4*)(ws1s + (g * 3 + v) * 100);
        float am = 0.f, ad = 0.f;
        #pragma unroll 5
        for (int k = 0; k < 25; k++) {
            float4 te = tr[k];
            float4 w = wr[k];
            float4 s_ = sr[k];
            am = fmaf(te.x, w.x, am); am = fmaf(te.y, w.y, am);
            am = fmaf(te.z, w.z, am); am = fmaf(te.w, w.w, am);
            ad = fmaf(te.x, s_.x, ad); ad = fmaf(te.y, s_.y, ad);
            ad = fmaf(te.z, s_.z, ad); ad = fmaf(te.w, s_.w, ad);
        }
        m2s[tid] = (am + c2s[v]) * SCALE;
        dss[tid] = ad;
    }
    __syncthreads();

    // softmax over T per (g,v)
    if (tid < 24) {
        int g = tid / 3, v = tid % 3;
        float mx = NEGBIG;
        #pragma unroll
        for (int t = 0; t < 10; t++) mx = fmaxf(mx, m2s[g * 30 + t * 3 + v]);
        float s = 0.f;
        #pragma unroll
        for (int t = 0; t < 10; t++) s += __expf(m2s[g * 30 + t * 3 + v] - mx);
        red2[tid] = mx;
        red2[24 + tid] = 1.0f / s;
    }
    __syncthreads();

    // out[b][t] = sum_v sm2[t][v] * d[t][v]
    if (tid < 80) {
        int g = tid / 10, t = tid % 10;
        float o = 0.f;
        #pragma unroll
        for (int v = 0; v < 3; v++) {
            float w = __expf(m2s[g * 30 + t * 3 + v] - red2[g * 3 + v]) * red2[24 + g * 3 + v];
            o = fmaf(w, dss[g * 30 + t * 3 + v], o);
        }
        out[(size_t)(b0 + g) * 10 + t] = o;
    }
}

// ---------------------------------------------------------------------------
extern "C" void kernel_launch(void* const* d_in, const int* in_sizes, int n_in,
                              void* d_out, int out_size) {
    const float* x     = (const float*)d_in[0];
    const float* tag   = (const float*)d_in[1];
    const float* vk    = (const float*)d_in[2];
    const float* fc1_w = (const float*)d_in[3];
    const float* fc1_b = (const float*)d_in[4];
    const float* fc2_w = (const float*)d_in[5];
    const float* fc2_b = (const float*)d_in[6];
    const float* fc3_w = (const float*)d_in[7];
    const float* fc3_b = (const float*)d_in[8];
    const float* fc4_w = (const float*)d_in[9];
    const float* fc4_b = (const float*)d_in[10];
    float* out = (float*)d_out;

    const int SMEM1 = 2 * 100 * XST * 4;   // 84800 B
    const int SMEM2 = (10600 + 2400 + 2400 + 300 + 100 + 4 + 240 + 240 + 48) * 4; // 65328 B
    cudaFuncSetAttribute(k_stage1, cudaFuncAttributeMaxDynamicSharedMemorySize, SMEM1);
    cudaFuncSetAttribute(k_stage2, cudaFuncAttributeMaxDynamicSharedMemorySize, SMEM2);

    k_pre_a<<<75, 256>>>(vk, fc2_w, fc2_b, fc3_w, fc3_b);
    k_pre_b<<<1, 1024>>>(fc1_w, fc1_b, fc4_w, fc4_b);
    k_stage1<<<8192 / NB, 256, SMEM1>>>(x);
    k_stage2<<<8192 / GB, 256, SMEM2>>>(tag, fc1_w, fc1_b, out);
}